// round 5
// baseline (speedup 1.0000x reference)
#include <cuda_runtime.h>

#define FLAT 12288
#define HID  4096
#define NS   16
#define KST  4
#define LRf  0.01f
#define RCH  192         // row chunks for W^T v partials
#define ROWS_PER_CH 64   // RCH * ROWS_PER_CH == FLAT
#define CTH  1024        // cheap-phase threads (single block)

// cheap-phase dynamic smem layout (floats):
// [0,HID) q0 | [HID,2H) s0 | [2H,3H) q1 | [3H,4H) s1 | [4H,4H+FLAT) r | red[96]
#define SM_R   (4 * HID)
#define SM_RED (4 * HID + FLAT)
#define SMEM_FLOATS (4 * HID + FLAT + 96)
#define SMEM_BYTES  (SMEM_FLOATS * 4)

// ---------------- device scratch (static, no runtime allocation) ----------------
__device__ float g_part[RCH * HID];   // gemvT partial column sums
__device__ float g_h[HID];            // dense-phase working h
__device__ float g_hA[HID];           // hinit_0 (q)
__device__ float g_hB[HID];           // hfinal_0 (s)
__device__ float g_vA[FLAT];          // vfinal_0 (r)

__device__ __forceinline__ float sigm(float x) { return 1.f / (1.f + __expf(-x)); }

// ---------------- dense phase: sample 0 with the real W ----------------

// partial column sums of W^T v: block = 256 threads x float2 (512 cols),
// blockIdx.y = 64-row chunk. grid (8, 192) = 1536 blocks (not grid-limited).
__global__ void k_gemvT(const float* __restrict__ W, const float* __restrict__ v) {
    __shared__ float sv[ROWS_PER_CH];
    int r0 = blockIdx.y * ROWS_PER_CH;
    if (threadIdx.x < ROWS_PER_CH) sv[threadIdx.x] = v[r0 + threadIdx.x];
    __syncthreads();
    int col2 = blockIdx.x * 256 + threadIdx.x;      // float2 column index
    const float2* Wp = (const float2*)W + (size_t)r0 * (HID / 2) + col2;
    float ax = 0.f, ay = 0.f;
#pragma unroll 8
    for (int r = 0; r < ROWS_PER_CH; r++) {
        float2 w = Wp[(size_t)r * (HID / 2)];
        float s = sv[r];
        ax += w.x * s;
        ay += w.y * s;
    }
    float2 o; o.x = ax; o.y = ay;
    ((float2*)g_part)[blockIdx.y * (HID / 2) + col2] = o;
}

// reduce partials + bias + sigmoid -> g_h; optionally save hinit/hfinal
__global__ void k_hred(const float* __restrict__ b, int save) {
    int j = blockIdx.x * 256 + threadIdx.x;
    float s = b[j];
#pragma unroll 8
    for (int r = 0; r < RCH; r++) s += g_part[r * HID + j];
    float h = sigm(s);
    g_h[j] = h;
    if (save == 1) g_hA[j] = h;        // hinit_0 (q for sample 1)
    else if (save == 2) g_hB[j] = h;   // hfinal_0 (s for sample 1)
}

// v = sigmoid(a + W h): one warp per row, 16 rows per 512-thread block
__global__ void k_gemv(const float* __restrict__ W, const float* __restrict__ a) {
    __shared__ float sh[HID];
    for (int k = threadIdx.x; k < HID; k += blockDim.x) sh[k] = g_h[k];
    __syncthreads();
    int warp = threadIdx.x >> 5, lane = threadIdx.x & 31;
    int row = blockIdx.x * 16 + warp;
    const float4* Wr = (const float4*)(W + (size_t)row * HID);
    float acc = 0.f;
#pragma unroll 8
    for (int i = lane; i < HID / 4; i += 32) {
        float4 w = Wr[i];
        float4 h4 = *(const float4*)&sh[4 * i];
        acc += w.x * h4.x + w.y * h4.y + w.z * h4.z + w.w * h4.w;
    }
#pragma unroll
    for (int o = 16; o; o >>= 1) acc += __shfl_down_sync(0xffffffffu, acc, o);
    if (lane == 0) g_vA[row] = sigm(a[row] + acc);
}

// ---------------- cheap phase: samples 1..15, rank-2 W, ONE block, SMEM-resident ----
// q,s (double-buffered) and r live entirely in shared memory; p streams from
// gmem (L1-hot after first of 4 steps). All 121 syncs are __syncthreads().

__device__ __forceinline__ float2 blockdot2(float a, float b, float* red) {
#pragma unroll
    for (int o = 16; o; o >>= 1) {
        a += __shfl_down_sync(0xffffffffu, a, o);
        b += __shfl_down_sync(0xffffffffu, b, o);
    }
    int w = threadIdx.x >> 5;
    if ((threadIdx.x & 31) == 0) { red[w] = a; red[32 + w] = b; }
    __syncthreads();
    if (threadIdx.x < 32) {
        float x = red[threadIdx.x], y = red[32 + threadIdx.x];
#pragma unroll
        for (int o = 16; o; o >>= 1) {
            x += __shfl_down_sync(0xffffffffu, x, o);
            y += __shfl_down_sync(0xffffffffu, y, o);
        }
        if (threadIdx.x == 0) { red[64] = x; red[65] = y; }
    }
    __syncthreads();
    float2 r; r.x = red[64]; r.y = red[65];
    return r;
}

__global__ void __launch_bounds__(CTH, 1) k_cheap(const float* __restrict__ inp,
                                                  float* __restrict__ out) {
    extern __shared__ float sm[];
    float* red = sm + SM_RED;
    float* sr  = sm + SM_R;
    const int tid = threadIdx.x;

    // preload carry state into smem (each thread touches only its own indices)
#pragma unroll
    for (int jj = 0; jj < HID / CTH; jj++) {
        int j = tid + jj * CTH;
        sm[j] = g_hA[j];            // q0
        sm[HID + j] = g_hB[j];      // s0
    }
#pragma unroll
    for (int kk = 0; kk < FLAT / CTH; kk++) {
        int k = tid + kk * CTH;
        sr[k] = g_vA[k];
    }
    __syncthreads();

    int qo = 0;                      // current q at sm[qo], s at sm[qo+HID]
    // entry dots: d1 = inputs[0].inputs[1], d2 = vfinal_0.inputs[1]
    float2 dv;
    {
        float a1 = 0.f, a2 = 0.f;
        const float* x0 = inp;
        const float* x1 = inp + FLAT;
#pragma unroll
        for (int kk = 0; kk < FLAT / CTH; kk++) {
            int k = tid + kk * CTH;
            float b_ = x1[k];
            a1 += x0[k] * b_;
            a2 += sr[k] * b_;
        }
        dv = blockdot2(a1, a2, red);
    }

    for (int i = 1; i < NS; i++) {
        const float* p  = inp + (size_t)(i - 1) * FLAT;   // v_init of prev sample
        const float* pn = inp + (size_t)i * FLAT;         // v_init of this sample
        const float* xn = inp + (size_t)(i + 1) * FLAT;   // next v_init (guarded)
        float* qc = sm + qo;
        float* sc = sm + qo + HID;
        float* qn = sm + (2 * HID - qo);
        float* sn = sm + (3 * HID - qo);
        for (int t = 1; t <= KST; t++) {
            // ---- h phase: h = sigm(LR*(q*(1+d1) - s*(1+d2))); dots q.h, s.h inline
            float c1 = 1.f + dv.x, c2 = 1.f + dv.y;
            float a3 = 0.f, a4 = 0.f;
            float* ht = (t == 1) ? qn : ((t == KST) ? sn : (float*)0);
#pragma unroll
            for (int jj = 0; jj < HID / CTH; jj++) {
                int j = tid + jj * CTH;
                float qj = qc[j], sj = sc[j];
                float h = sigm(LRf * (qj * c1 - sj * c2));
                if (ht) ht[j] = h;
                a3 += qj * h;
                a4 += sj * h;
            }
            float2 dh = blockdot2(a3, a4, red);

            // ---- v phase: v = sigm(LR*(p*(1+d3) - r*(1+d4))); next dots inline
            float c3 = 1.f + dh.x, c4 = 1.f + dh.y;
            float a1 = 0.f, a2 = 0.f;
            if (t < KST) {
#pragma unroll
                for (int kk = 0; kk < FLAT / CTH; kk++) {
                    int k = tid + kk * CTH;
                    float pk = p[k], rk = sr[k];
                    float v = sigm(LRf * (pk * c3 - rk * c4));
                    a1 += pk * v;          // p.v for next step
                    a2 += rk * v;          // r.v for next step
                }
            } else if (i < NS - 1) {
#pragma unroll
                for (int kk = 0; kk < FLAT / CTH; kk++) {
                    int k = tid + kk * CTH;
                    float pk = p[k], rk = sr[k];
                    float v = sigm(LRf * (pk * c3 - rk * c4));
                    sr[k] = v;                         // in-place: vfinal_i -> r
                    float xnk = xn[k];
                    a1 += pn[k] * xnk;                 // inputs[i].inputs[i+1]
                    a2 += v * xnk;                     // vfinal_i.inputs[i+1]
                }
            } else {
#pragma unroll
                for (int kk = 0; kk < FLAT / CTH; kk++) {
                    int k = tid + kk * CTH;
                    float pk = p[k], rk = sr[k];
                    float v = sigm(LRf * (pk * c3 - rk * c4));
                    out[k] = v;                        // final reconstruction
                }
            }
            dv = blockdot2(a1, a2, red);
        }
        qo = 2 * HID - qo;           // swap q/s double buffers
    }
}

// ---------------- launch ----------------

extern "C" void kernel_launch(void* const* d_in, const int* in_sizes, int n_in,
                              void* d_out, int out_size) {
    const float* inp = (const float*)d_in[0];  // (16, 64, 64, 3) = 16 x 12288
    const float* W   = (const float*)d_in[1];  // (12288, 4096)
    const float* a   = (const float*)d_in[2];  // (12288, 1)
    const float* b   = (const float*)d_in[3];  // (4096, 1)
    float* out = (float*)d_out;                // (12288, 1)

    float* vA = 0;
    cudaGetSymbolAddress((void**)&vA, g_vA);
    cudaFuncSetAttribute(k_cheap, cudaFuncAttributeMaxDynamicSharedMemorySize,
                         SMEM_BYTES);

    dim3 gT(HID / 512, RCH);
    for (int s = 0; s < KST; s++) {
        const float* v = (s == 0) ? inp : vA;
        k_gemvT<<<gT, 256>>>(W, v);
        k_hred<<<HID / 256, 256>>>(b, (s == 0) ? 1 : ((s == KST - 1) ? 2 : 0));
        k_gemv<<<FLAT / 16, 512>>>(W, a);
    }
    k_cheap<<<1, CTH, SMEM_BYTES>>>(inp, out);
}